// round 1
// baseline (speedup 1.0000x reference)
#include <cuda_runtime.h>
#include <cuda_bf16.h>

// Problem: B=16, C=1024, HW=1024, fp32.
// scores = b_f @ c_f^T  (per-batch 1024x1024x1024 NT GEMM)
// P      = softmax(scores, axis=-1)
// out    = P @ a_f + a   (per-batch 1024x1024x1024 NN GEMM + residual)

#define BATCH 16
#define MDIM 1024   // C
#define KDIM 1024   // HW (gemm1) / C (gemm2)

// 64 MB scratch for scores / softmax probabilities
__device__ float g_scores[(size_t)BATCH * MDIM * MDIM];

#define BM 128
#define BN 128
#define BK 8
#define TM 8
#define TN 8
// 256 threads: 16x16 grid of 8x8 microtiles

// ---------------------------------------------------------------------------
// GEMM1 (NT): S[i][j] = sum_k X[i][k] * Y[j][k]
// X, Y row-major [1024,1024] per batch, K contiguous in both.
// ---------------------------------------------------------------------------
__global__ __launch_bounds__(256, 2)
void cam_gemm_nt(const float* __restrict__ X, const float* __restrict__ Y,
                 float* __restrict__ S) {
    __shared__ float As[BK][BM];
    __shared__ float Bs[BK][BN];

    const int b = blockIdx.z;
    const float* Xb = X + (size_t)b * MDIM * KDIM;
    const float* Yb = Y + (size_t)b * MDIM * KDIM;
    float* Sb = S + (size_t)b * MDIM * MDIM;

    const int tid  = threadIdx.x;
    const int row0 = blockIdx.y * BM;
    const int col0 = blockIdx.x * BN;

    // loader mapping: each thread loads one float4 per tile
    const int lrow = tid >> 1;            // 0..127
    const int lk4  = (tid & 1) * 4;       // 0 or 4

    // compute mapping
    const int trow = (tid >> 4) * TM;     // 0..120
    const int tcol = (tid & 15) * TN;     // 0..120

    float acc[TM][TN];
#pragma unroll
    for (int i = 0; i < TM; i++)
#pragma unroll
        for (int j = 0; j < TN; j++) acc[i][j] = 0.f;

    const float* xptr = Xb + (size_t)(row0 + lrow) * KDIM + lk4;
    const float* yptr = Yb + (size_t)(col0 + lrow) * KDIM + lk4;

    for (int k0 = 0; k0 < KDIM; k0 += BK) {
        float4 xa = *(const float4*)(xptr + k0);
        float4 ya = *(const float4*)(yptr + k0);
        __syncthreads();
        As[lk4 + 0][lrow] = xa.x; As[lk4 + 1][lrow] = xa.y;
        As[lk4 + 2][lrow] = xa.z; As[lk4 + 3][lrow] = xa.w;
        Bs[lk4 + 0][lrow] = ya.x; Bs[lk4 + 1][lrow] = ya.y;
        Bs[lk4 + 2][lrow] = ya.z; Bs[lk4 + 3][lrow] = ya.w;
        __syncthreads();

#pragma unroll
        for (int k = 0; k < BK; k++) {
            float ar[TM], br[TN];
            *(float4*)&ar[0] = *(const float4*)&As[k][trow];
            *(float4*)&ar[4] = *(const float4*)&As[k][trow + 4];
            *(float4*)&br[0] = *(const float4*)&Bs[k][tcol];
            *(float4*)&br[4] = *(const float4*)&Bs[k][tcol + 4];
#pragma unroll
            for (int i = 0; i < TM; i++)
#pragma unroll
                for (int j = 0; j < TN; j++)
                    acc[i][j] = fmaf(ar[i], br[j], acc[i][j]);
        }
    }

#pragma unroll
    for (int i = 0; i < TM; i++) {
        float* srow = Sb + (size_t)(row0 + trow + i) * MDIM + col0 + tcol;
        *(float4*)(srow)     = make_float4(acc[i][0], acc[i][1], acc[i][2], acc[i][3]);
        *(float4*)(srow + 4) = make_float4(acc[i][4], acc[i][5], acc[i][6], acc[i][7]);
    }
}

// ---------------------------------------------------------------------------
// Row softmax over last dim (1024) in place. One block per row.
// ---------------------------------------------------------------------------
__global__ __launch_bounds__(256)
void cam_softmax(float* __restrict__ S) {
    __shared__ float red[256];
    const size_t row = blockIdx.x;
    float* p = S + row * MDIM;
    const int tid = threadIdx.x;

    float4 v = *(const float4*)(p + tid * 4);
    float m = fmaxf(fmaxf(v.x, v.y), fmaxf(v.z, v.w));
    red[tid] = m;
    __syncthreads();
    for (int s = 128; s > 0; s >>= 1) {
        if (tid < s) red[tid] = fmaxf(red[tid], red[tid + s]);
        __syncthreads();
    }
    m = red[0];
    __syncthreads();

    v.x = __expf(v.x - m); v.y = __expf(v.y - m);
    v.z = __expf(v.z - m); v.w = __expf(v.w - m);
    float sum = v.x + v.y + v.z + v.w;
    red[tid] = sum;
    __syncthreads();
    for (int s = 128; s > 0; s >>= 1) {
        if (tid < s) red[tid] += red[tid + s];
        __syncthreads();
    }
    const float inv = 1.0f / red[0];
    v.x *= inv; v.y *= inv; v.z *= inv; v.w *= inv;
    *(float4*)(p + tid * 4) = v;
}

// ---------------------------------------------------------------------------
// GEMM2 (NN) + residual: O[i][k] = sum_j P[i][j] * A[j][k] + Ares[i][k]
// ---------------------------------------------------------------------------
__global__ __launch_bounds__(256, 2)
void cam_gemm_nn_res(const float* __restrict__ P, const float* __restrict__ A,
                     const float* __restrict__ Ares, float* __restrict__ O) {
    __shared__ float Ps[BK][BM];
    __shared__ float Qs[BK][BN];

    const int b = blockIdx.z;
    const float* Pb = P + (size_t)b * MDIM * MDIM;
    const float* Ab = A + (size_t)b * MDIM * KDIM;
    const float* Rb = Ares + (size_t)b * MDIM * KDIM;
    float* Ob = O + (size_t)b * MDIM * KDIM;

    const int tid  = threadIdx.x;
    const int row0 = blockIdx.y * BM;   // i
    const int col0 = blockIdx.x * BN;   // k

    // P tile loader (transposed store): [128 i][8 j]
    const int lrow = tid >> 1;           // i local
    const int lk4  = (tid & 1) * 4;      // j local base

    // A tile loader (straight store): [8 j][128 k]
    const int arow  = tid >> 5;          // j local 0..7
    const int acol4 = (tid & 31) * 4;    // k local

    const int trow = (tid >> 4) * TM;
    const int tcol = (tid & 15) * TN;

    float acc[TM][TN];
#pragma unroll
    for (int i = 0; i < TM; i++)
#pragma unroll
        for (int j = 0; j < TN; j++) acc[i][j] = 0.f;

    const float* pptr = Pb + (size_t)(row0 + lrow) * MDIM + lk4;
    const float* aptr = Ab + (size_t)arow * KDIM + col0 + acol4;

    for (int j0 = 0; j0 < MDIM; j0 += BK) {
        float4 pa = *(const float4*)(pptr + j0);
        float4 aa = *(const float4*)(aptr + (size_t)j0 * KDIM);
        __syncthreads();
        Ps[lk4 + 0][lrow] = pa.x; Ps[lk4 + 1][lrow] = pa.y;
        Ps[lk4 + 2][lrow] = pa.z; Ps[lk4 + 3][lrow] = pa.w;
        *(float4*)&Qs[arow][acol4] = aa;
        __syncthreads();

#pragma unroll
        for (int k = 0; k < BK; k++) {
            float ar[TM], br[TN];
            *(float4*)&ar[0] = *(const float4*)&Ps[k][trow];
            *(float4*)&ar[4] = *(const float4*)&Ps[k][trow + 4];
            *(float4*)&br[0] = *(const float4*)&Qs[k][tcol];
            *(float4*)&br[4] = *(const float4*)&Qs[k][tcol + 4];
#pragma unroll
            for (int i = 0; i < TM; i++)
#pragma unroll
                for (int j = 0; j < TN; j++)
                    acc[i][j] = fmaf(ar[i], br[j], acc[i][j]);
        }
    }

#pragma unroll
    for (int i = 0; i < TM; i++) {
        const float* rrow = Rb + (size_t)(row0 + trow + i) * KDIM + col0 + tcol;
        float* orow = Ob + (size_t)(row0 + trow + i) * KDIM + col0 + tcol;
        float4 r0 = *(const float4*)(rrow);
        float4 r1 = *(const float4*)(rrow + 4);
        *(float4*)(orow) = make_float4(acc[i][0] + r0.x, acc[i][1] + r0.y,
                                       acc[i][2] + r0.z, acc[i][3] + r0.w);
        *(float4*)(orow + 4) = make_float4(acc[i][4] + r1.x, acc[i][5] + r1.y,
                                           acc[i][6] + r1.z, acc[i][7] + r1.w);
    }
}

extern "C" void kernel_launch(void* const* d_in, const int* in_sizes, int n_in,
                              void* d_out, int out_size) {
    const float* a = (const float*)d_in[0];
    const float* b = (const float*)d_in[1];
    const float* c = (const float*)d_in[2];
    float* out = (float*)d_out;

    float* scores = nullptr;
    cudaGetSymbolAddress((void**)&scores, g_scores);

    dim3 block(256);
    dim3 grid(MDIM / BN, MDIM / BM, BATCH);

    // 1) scores = b_f @ c_f^T
    cam_gemm_nt<<<grid, block>>>(b, c, scores);
    // 2) row softmax in place
    cam_softmax<<<BATCH * MDIM, 256>>>(scores);
    // 3) out = P @ a_f + a
    cam_gemm_nn_res<<<grid, block>>>(scores, a, a, out);
}

// round 3
// speedup vs baseline: 2.9478x; 2.9478x over previous
#include <cuda_runtime.h>
#include <cuda_bf16.h>
#include <cstdint>

// ============================================================================
// CAM: scores = b@c^T (NT), P = softmax(scores), out = P@a + a   per batch.
// B=16, C=1024, HW=1024. Split-bf16 mma.sync GEMMs (hi*hi + hi*lo + lo*hi),
// fp32 accumulate. Base-ISA only (no tcgen05 — harness targets sm_103).
// ============================================================================

#define BATCH 16
#define NDIM 1024

// -------- scratch (device globals; no allocation allowed) --------
__device__ __nv_bfloat16 g_b_hi[(size_t)BATCH * NDIM * NDIM];
__device__ __nv_bfloat16 g_b_lo[(size_t)BATCH * NDIM * NDIM];
__device__ __nv_bfloat16 g_c_hi[(size_t)BATCH * NDIM * NDIM];
__device__ __nv_bfloat16 g_c_lo[(size_t)BATCH * NDIM * NDIM];
__device__ __nv_bfloat16 g_at_hi[(size_t)BATCH * NDIM * NDIM];
__device__ __nv_bfloat16 g_at_lo[(size_t)BATCH * NDIM * NDIM];
__device__ __nv_bfloat16 g_p_hi[(size_t)BATCH * NDIM * NDIM];
__device__ __nv_bfloat16 g_p_lo[(size_t)BATCH * NDIM * NDIM];
__device__ float g_scores[(size_t)BATCH * NDIM * NDIM];

__device__ __forceinline__ uint32_t smem_u32(const void* p) {
    uint32_t a;
    asm("{ .reg .u64 t; cvta.to.shared.u64 t, %1; cvt.u32.u64 %0, t; }"
        : "=r"(a) : "l"(p));
    return a;
}

#define LDSM4(r0, r1, r2, r3, addr) \
    asm volatile("ldmatrix.sync.aligned.m8n8.x4.shared.b16 {%0,%1,%2,%3}, [%4];" \
                 : "=r"(r0), "=r"(r1), "=r"(r2), "=r"(r3) : "r"(addr))

#define MMA16816(d, a, bb0, bb1) \
    asm volatile("mma.sync.aligned.m16n8k16.row.col.f32.bf16.bf16.f32 " \
                 "{%0,%1,%2,%3}, {%4,%5,%6,%7}, {%8,%9}, {%0,%1,%2,%3};" \
                 : "+f"((d)[0]), "+f"((d)[1]), "+f"((d)[2]), "+f"((d)[3]) \
                 : "r"((a)[0]), "r"((a)[1]), "r"((a)[2]), "r"((a)[3]), \
                   "r"(bb0), "r"(bb1))

// SW128 swizzle, 128B rows: chunk' = chunk ^ (row & 7)
__device__ __forceinline__ uint32_t swz(uint32_t base, int row, int ch) {
    return base + (uint32_t)(row * 128) + (uint32_t)(((ch ^ (row & 7)) & 7) * 16);
}

// ============================================================================
// 1) Split fp32 -> bf16 hi/lo (elementwise), vectorized
// ============================================================================
__global__ __launch_bounds__(256)
void split_bf16(const float* __restrict__ src, __nv_bfloat16* __restrict__ hi,
                __nv_bfloat16* __restrict__ lo) {
    size_t i = (size_t)blockIdx.x * blockDim.x + threadIdx.x;
    float4 v = ((const float4*)src)[i];
    __nv_bfloat162 h0 = __floats2bfloat162_rn(v.x, v.y);
    __nv_bfloat162 h1 = __floats2bfloat162_rn(v.z, v.w);
    float lx = v.x - __bfloat162float(h0.x);
    float ly = v.y - __bfloat162float(h0.y);
    float lz = v.z - __bfloat162float(h1.x);
    float lw = v.w - __bfloat162float(h1.y);
    ((__nv_bfloat162*)hi)[i * 2]     = h0;
    ((__nv_bfloat162*)hi)[i * 2 + 1] = h1;
    ((__nv_bfloat162*)lo)[i * 2]     = __floats2bfloat162_rn(lx, ly);
    ((__nv_bfloat162*)lo)[i * 2 + 1] = __floats2bfloat162_rn(lz, lw);
}

// ============================================================================
// 2) Transpose a[b][ch][hw] -> a_t[b][hw][ch], split to bf16 hi/lo
// ============================================================================
__global__ __launch_bounds__(256)
void transpose_split(const float* __restrict__ a, __nv_bfloat16* __restrict__ at_hi,
                     __nv_bfloat16* __restrict__ at_lo) {
    __shared__ float tile[32][33];
    const size_t base = (size_t)blockIdx.z * NDIM * NDIM;
    const int tx = threadIdx.x, ty = threadIdx.y;
    const int x = blockIdx.x * 32 + tx;
    const int y0 = blockIdx.y * 32;
#pragma unroll
    for (int j = 0; j < 4; j++)
        tile[ty + j * 8][tx] = a[base + (size_t)(y0 + ty + j * 8) * NDIM + x];
    __syncthreads();
    const int x2 = blockIdx.y * 32 + tx;
    const int y20 = blockIdx.x * 32;
#pragma unroll
    for (int j = 0; j < 4; j++) {
        float v = tile[tx][ty + j * 8];
        __nv_bfloat16 h = __float2bfloat16(v);
        float l = v - __bfloat162float(h);
        size_t o = base + (size_t)(y20 + ty + j * 8) * NDIM + x2;
        at_hi[o] = h;
        at_lo[o] = __float2bfloat16(l);
    }
}

// ============================================================================
// 3) Row softmax (1024) -> bf16 hi/lo P
// ============================================================================
__global__ __launch_bounds__(256)
void cam_softmax(const float* __restrict__ S, __nv_bfloat16* __restrict__ Phi,
                 __nv_bfloat16* __restrict__ Plo) {
    __shared__ float red[256];
    const size_t row = blockIdx.x;
    const float* p = S + row * NDIM;
    const int tid = threadIdx.x;

    float4 v = *(const float4*)(p + tid * 4);
    float m = fmaxf(fmaxf(v.x, v.y), fmaxf(v.z, v.w));
    red[tid] = m;
    __syncthreads();
    for (int s = 128; s > 0; s >>= 1) {
        if (tid < s) red[tid] = fmaxf(red[tid], red[tid + s]);
        __syncthreads();
    }
    m = red[0];
    __syncthreads();

    v.x = __expf(v.x - m); v.y = __expf(v.y - m);
    v.z = __expf(v.z - m); v.w = __expf(v.w - m);
    red[tid] = v.x + v.y + v.z + v.w;
    __syncthreads();
    for (int s = 128; s > 0; s >>= 1) {
        if (tid < s) red[tid] += red[tid + s];
        __syncthreads();
    }
    const float inv = 1.0f / red[0];
    v.x *= inv; v.y *= inv; v.z *= inv; v.w *= inv;

    __nv_bfloat162 h0 = __floats2bfloat162_rn(v.x, v.y);
    __nv_bfloat162 h1 = __floats2bfloat162_rn(v.z, v.w);
    float lx = v.x - __bfloat162float(h0.x);
    float ly = v.y - __bfloat162float(h0.y);
    float lz = v.z - __bfloat162float(h1.x);
    float lw = v.w - __bfloat162float(h1.y);
    ((__nv_bfloat162*)(Phi + row * NDIM))[tid * 2]     = h0;
    ((__nv_bfloat162*)(Phi + row * NDIM))[tid * 2 + 1] = h1;
    ((__nv_bfloat162*)(Plo + row * NDIM))[tid * 2]     = __floats2bfloat162_rn(lx, ly);
    ((__nv_bfloat162*)(Plo + row * NDIM))[tid * 2 + 1] = __floats2bfloat162_rn(lz, lw);
}

// ============================================================================
// 4) Split-bf16 NT GEMM via mma.sync: D[i][j] = sum_k (Ah+Al)[i][k]*(Bh+Bl)[j][k]
//    CTA tile 128x128, K-chunk 64, 2-stage cp.async. 8 warps = 2(M) x 4(N),
//    warp tile 64x32. RES: += resid.
// ============================================================================
#define KC 64
#define TILE_B 16384          // 128 rows x 128B (64 bf16)
#define STAGE_B 65536         // Ahi, Alo, Bhi, Blo
#define SMEM_DYN (1024 + 2 * STAGE_B)

template<bool RES>
__global__ __launch_bounds__(256, 1)
void cam_mma_kernel(const __nv_bfloat16* __restrict__ Ahi_g, const __nv_bfloat16* __restrict__ Alo_g,
                    const __nv_bfloat16* __restrict__ Bhi_g, const __nv_bfloat16* __restrict__ Blo_g,
                    const float* __restrict__ resid, float* __restrict__ outp)
{
    extern __shared__ char smem_raw[];
    char* sbase_p = (char*)((((uintptr_t)smem_raw) + 1023) & ~(uintptr_t)1023);
    const uint32_t sbase = smem_u32(sbase_p);

    const int tid = threadIdx.x;
    const int l   = tid & 31;
    const int wid = tid >> 5;
    const int wm  = wid >> 2;           // 0..1
    const int wn  = wid & 3;            // 0..3
    const int m0  = wm * 64;
    const int n0  = wn * 32;

    const size_t bofs = (size_t)blockIdx.z * NDIM * NDIM;
    const int row0 = blockIdx.y * 128;
    const int col0 = blockIdx.x * 128;
    const __nv_bfloat16* s0 = Ahi_g + bofs + (size_t)row0 * NDIM;
    const __nv_bfloat16* s1 = Alo_g + bofs + (size_t)row0 * NDIM;
    const __nv_bfloat16* s2 = Bhi_g + bofs + (size_t)col0 * NDIM;
    const __nv_bfloat16* s3 = Blo_g + bofs + (size_t)col0 * NDIM;

    // ---- async loader: one K-chunk (64 cols) of 4 tiles, SW128-swizzled ----
    auto load_chunk = [&](int c, int buf) {
        const int k0 = c * KC;
        const uint32_t stage = sbase + (uint32_t)buf * STAGE_B;
#pragma unroll
        for (int t = 0; t < 4; t++) {
            const __nv_bfloat16* sp = (t == 0) ? s0 : (t == 1) ? s1 : (t == 2) ? s2 : s3;
#pragma unroll
            for (int jj = 0; jj < 4; jj++) {
                int slot = tid + 256 * jj;        // 0..1023
                int row  = slot >> 3;             // 0..127
                int k16  = slot & 7;              // 16B chunk in 128B row
                uint32_t dst = swz(stage + (uint32_t)t * TILE_B, row, k16);
                const __nv_bfloat16* src = sp + (size_t)row * NDIM + k0 + k16 * 8;
                asm volatile("cp.async.cg.shared.global [%0], [%1], 16;"
                             :: "r"(dst), "l"(src));
            }
        }
        asm volatile("cp.async.commit_group;" ::: "memory");
    };

    float acc[4][4][4];
#pragma unroll
    for (int i = 0; i < 4; i++)
#pragma unroll
        for (int j = 0; j < 4; j++)
#pragma unroll
            for (int q = 0; q < 4; q++) acc[i][j][q] = 0.f;

    // ldmatrix lane address components
    const int a_row = l & 15;
    const int a_cs  = l >> 4;                       // 0/1
    const int b_row = (l & 7) + ((l >> 4) << 3);    // 0..15
    const int b_cs  = (l >> 3) & 1;                 // 0/1

    load_chunk(0, 0);
    load_chunk(1, 1);

    for (int c = 0; c < 16; c++) {
        const int buf = c & 1;
        if (c >= 14) { asm volatile("cp.async.wait_group 0;" ::: "memory"); }
        else         { asm volatile("cp.async.wait_group 1;" ::: "memory"); }
        __syncthreads();

        const uint32_t st  = sbase + (uint32_t)buf * STAGE_B;
        const uint32_t aHi = st;
        const uint32_t aLo = st + TILE_B;
        const uint32_t bHi = st + 2 * TILE_B;
        const uint32_t bLo = st + 3 * TILE_B;

#pragma unroll
        for (int k16 = 0; k16 < 4; k16++) {
            const int chA = 2 * k16 + a_cs;
            const int chB = 2 * k16 + b_cs;

            uint32_t ah[4][4], al[4][4];
#pragma unroll
            for (int i = 0; i < 4; i++) {
                const int r = m0 + i * 16 + a_row;
                LDSM4(ah[i][0], ah[i][1], ah[i][2], ah[i][3], swz(aHi, r, chA));
                LDSM4(al[i][0], al[i][1], al[i][2], al[i][3], swz(aLo, r, chA));
            }
            uint32_t bh[4][2], bl[4][2];
#pragma unroll
            for (int j = 0; j < 2; j++) {
                const int r = n0 + j * 16 + b_row;
                LDSM4(bh[2*j][0], bh[2*j][1], bh[2*j+1][0], bh[2*j+1][1], swz(bHi, r, chB));
                LDSM4(bl[2*j][0], bl[2*j][1], bl[2*j+1][0], bl[2*j+1][1], swz(bLo, r, chB));
            }
#pragma unroll
            for (int i = 0; i < 4; i++)
#pragma unroll
                for (int j = 0; j < 4; j++) {
                    MMA16816(acc[i][j], ah[i], bh[j][0], bh[j][1]);
                    MMA16816(acc[i][j], ah[i], bl[j][0], bl[j][1]);
                    MMA16816(acc[i][j], al[i], bh[j][0], bh[j][1]);
                }
        }
        __syncthreads();
        if (c + 2 < 16) load_chunk(c + 2, buf);
    }

    // ---- epilogue: regs -> gmem (float2, fused residual) ----
    float* outb = outp + bofs;
    const float* resb = resid + bofs;
    const int er = l >> 2;                 // 0..7
    const int ec = (l & 3) * 2;            // 0,2,4,6

#pragma unroll
    for (int i = 0; i < 4; i++) {
        const int grow = row0 + m0 + i * 16 + er;
#pragma unroll
        for (int j = 0; j < 4; j++) {
            const int gcol = col0 + n0 + j * 8 + ec;
            size_t o0 = (size_t)grow * NDIM + gcol;
            size_t o1 = (size_t)(grow + 8) * NDIM + gcol;
            float2 v0 = make_float2(acc[i][j][0], acc[i][j][1]);
            float2 v1 = make_float2(acc[i][j][2], acc[i][j][3]);
            if (RES) {
                float2 r0 = *(const float2*)(resb + o0);
                float2 r1 = *(const float2*)(resb + o1);
                v0.x += r0.x; v0.y += r0.y;
                v1.x += r1.x; v1.y += r1.y;
            }
            *(float2*)(outb + o0) = v0;
            *(float2*)(outb + o1) = v1;
        }
    }
}

// ============================================================================
extern "C" void kernel_launch(void* const* d_in, const int* in_sizes, int n_in,
                              void* d_out, int out_size) {
    const float* a = (const float*)d_in[0];
    const float* b = (const float*)d_in[1];
    const float* c = (const float*)d_in[2];
    float* out = (float*)d_out;

    __nv_bfloat16 *b_hi, *b_lo, *c_hi, *c_lo, *at_hi, *at_lo, *p_hi, *p_lo;
    float* scores;
    cudaGetSymbolAddress((void**)&b_hi, g_b_hi);
    cudaGetSymbolAddress((void**)&b_lo, g_b_lo);
    cudaGetSymbolAddress((void**)&c_hi, g_c_hi);
    cudaGetSymbolAddress((void**)&c_lo, g_c_lo);
    cudaGetSymbolAddress((void**)&at_hi, g_at_hi);
    cudaGetSymbolAddress((void**)&at_lo, g_at_lo);
    cudaGetSymbolAddress((void**)&p_hi, g_p_hi);
    cudaGetSymbolAddress((void**)&p_lo, g_p_lo);
    cudaGetSymbolAddress((void**)&scores, g_scores);

    cudaFuncSetAttribute((const void*)cam_mma_kernel<false>,
                         cudaFuncAttributeMaxDynamicSharedMemorySize, SMEM_DYN);
    cudaFuncSetAttribute((const void*)cam_mma_kernel<true>,
                         cudaFuncAttributeMaxDynamicSharedMemorySize, SMEM_DYN);

    const int n4 = (BATCH * NDIM * NDIM) / 4;
    split_bf16<<<n4 / 256, 256>>>(b, b_hi, b_lo);
    split_bf16<<<n4 / 256, 256>>>(c, c_hi, c_lo);
    transpose_split<<<dim3(32, 32, BATCH), dim3(32, 8)>>>(a, at_hi, at_lo);

    dim3 grid(8, 8, BATCH);
    // scores = b @ c^T
    cam_mma_kernel<false><<<grid, 256, SMEM_DYN>>>(b_hi, b_lo, c_hi, c_lo, a, scores);
    // P = softmax(scores) as bf16 hi/lo
    cam_softmax<<<BATCH * NDIM, 256>>>(scores, p_hi, p_lo);
    // out = P @ a^T(per-hw-major) + a
    cam_mma_kernel<true><<<grid, 256, SMEM_DYN>>>(p_hi, p_lo, at_hi, at_lo, a, out);
}

// round 4
// speedup vs baseline: 3.0286x; 1.0274x over previous
#include <cuda_runtime.h>
#include <cuda_bf16.h>
#include <cstdint>

// ============================================================================
// CAM: scores = b@c^T (NT), P = softmax(scores), out = P@a + a   per batch.
// B=16, C=1024, HW=1024. Split-bf16 mma.sync GEMMs (hi*hi + hi*lo + lo*hi),
// fp32 accumulate. Base-ISA only (harness targets sm_103, no tcgen05).
// R4: KC=32, 32KB stages, 2 CTAs/SM for tensor-pipe gap filling.
// ============================================================================

#define BATCH 16
#define NDIM 1024

// -------- scratch (device globals; no allocation allowed) --------
__device__ __nv_bfloat16 g_b_hi[(size_t)BATCH * NDIM * NDIM];
__device__ __nv_bfloat16 g_b_lo[(size_t)BATCH * NDIM * NDIM];
__device__ __nv_bfloat16 g_c_hi[(size_t)BATCH * NDIM * NDIM];
__device__ __nv_bfloat16 g_c_lo[(size_t)BATCH * NDIM * NDIM];
__device__ __nv_bfloat16 g_at_hi[(size_t)BATCH * NDIM * NDIM];
__device__ __nv_bfloat16 g_at_lo[(size_t)BATCH * NDIM * NDIM];
__device__ __nv_bfloat16 g_p_hi[(size_t)BATCH * NDIM * NDIM];
__device__ __nv_bfloat16 g_p_lo[(size_t)BATCH * NDIM * NDIM];
__device__ float g_scores[(size_t)BATCH * NDIM * NDIM];

__device__ __forceinline__ uint32_t smem_u32(const void* p) {
    uint32_t a;
    asm("{ .reg .u64 t; cvta.to.shared.u64 t, %1; cvt.u32.u64 %0, t; }"
        : "=r"(a) : "l"(p));
    return a;
}

#define LDSM4(r0, r1, r2, r3, addr) \
    asm volatile("ldmatrix.sync.aligned.m8n8.x4.shared.b16 {%0,%1,%2,%3}, [%4];" \
                 : "=r"(r0), "=r"(r1), "=r"(r2), "=r"(r3) : "r"(addr))

#define MMA16816(d, a, bb0, bb1) \
    asm volatile("mma.sync.aligned.m16n8k16.row.col.f32.bf16.bf16.f32 " \
                 "{%0,%1,%2,%3}, {%4,%5,%6,%7}, {%8,%9}, {%0,%1,%2,%3};" \
                 : "+f"((d)[0]), "+f"((d)[1]), "+f"((d)[2]), "+f"((d)[3]) \
                 : "r"((a)[0]), "r"((a)[1]), "r"((a)[2]), "r"((a)[3]), \
                   "r"(bb0), "r"(bb1))

// 64B-row swizzle: 4 chunks of 16B per row. granule(row,ch)=(4*row+ch')%8
// ch' = ch ^ ((row>>1)&3) makes any 8 consecutive rows hit 8 distinct granules.
__device__ __forceinline__ uint32_t swz64(uint32_t base, int row, int ch) {
    return base + (uint32_t)(row * 64) +
           (uint32_t)(((ch ^ ((row >> 1) & 3)) & 3) * 16);
}

// ============================================================================
// 1) Fused split fp32 -> bf16 hi/lo for b and c (grid.y selects tensor)
// ============================================================================
__global__ __launch_bounds__(256)
void split_bf16_2(const float* __restrict__ b, const float* __restrict__ c,
                  __nv_bfloat16* __restrict__ b_hi, __nv_bfloat16* __restrict__ b_lo,
                  __nv_bfloat16* __restrict__ c_hi, __nv_bfloat16* __restrict__ c_lo) {
    const float* src = blockIdx.y ? c : b;
    __nv_bfloat16* hi = blockIdx.y ? c_hi : b_hi;
    __nv_bfloat16* lo = blockIdx.y ? c_lo : b_lo;
    size_t i = (size_t)blockIdx.x * blockDim.x + threadIdx.x;
    float4 v = ((const float4*)src)[i];
    __nv_bfloat162 h0 = __floats2bfloat162_rn(v.x, v.y);
    __nv_bfloat162 h1 = __floats2bfloat162_rn(v.z, v.w);
    float lx = v.x - __bfloat162float(h0.x);
    float ly = v.y - __bfloat162float(h0.y);
    float lz = v.z - __bfloat162float(h1.x);
    float lw = v.w - __bfloat162float(h1.y);
    ((__nv_bfloat162*)hi)[i * 2]     = h0;
    ((__nv_bfloat162*)hi)[i * 2 + 1] = h1;
    ((__nv_bfloat162*)lo)[i * 2]     = __floats2bfloat162_rn(lx, ly);
    ((__nv_bfloat162*)lo)[i * 2 + 1] = __floats2bfloat162_rn(lz, lw);
}

// ============================================================================
// 2) Transpose a[b][ch][hw] -> a_t[b][hw][ch], split to bf16 hi/lo
// ============================================================================
__global__ __launch_bounds__(256)
void transpose_split(const float* __restrict__ a, __nv_bfloat16* __restrict__ at_hi,
                     __nv_bfloat16* __restrict__ at_lo) {
    __shared__ float tile[32][33];
    const size_t base = (size_t)blockIdx.z * NDIM * NDIM;
    const int tx = threadIdx.x, ty = threadIdx.y;
    const int x = blockIdx.x * 32 + tx;
    const int y0 = blockIdx.y * 32;
#pragma unroll
    for (int j = 0; j < 4; j++)
        tile[ty + j * 8][tx] = a[base + (size_t)(y0 + ty + j * 8) * NDIM + x];
    __syncthreads();
    const int x2 = blockIdx.y * 32 + tx;
    const int y20 = blockIdx.x * 32;
#pragma unroll
    for (int j = 0; j < 4; j++) {
        float v = tile[tx][ty + j * 8];
        __nv_bfloat16 h = __float2bfloat16(v);
        float l = v - __bfloat162float(h);
        size_t o = base + (size_t)(y20 + ty + j * 8) * NDIM + x2;
        at_hi[o] = h;
        at_lo[o] = __float2bfloat16(l);
    }
}

// ============================================================================
// 3) Row softmax (1024) -> bf16 hi/lo P
// ============================================================================
__global__ __launch_bounds__(256)
void cam_softmax(const float* __restrict__ S, __nv_bfloat16* __restrict__ Phi,
                 __nv_bfloat16* __restrict__ Plo) {
    __shared__ float red[256];
    const size_t row = blockIdx.x;
    const float* p = S + row * NDIM;
    const int tid = threadIdx.x;

    float4 v = *(const float4*)(p + tid * 4);
    float m = fmaxf(fmaxf(v.x, v.y), fmaxf(v.z, v.w));
    red[tid] = m;
    __syncthreads();
    for (int s = 128; s > 0; s >>= 1) {
        if (tid < s) red[tid] = fmaxf(red[tid], red[tid + s]);
        __syncthreads();
    }
    m = red[0];
    __syncthreads();

    v.x = __expf(v.x - m); v.y = __expf(v.y - m);
    v.z = __expf(v.z - m); v.w = __expf(v.w - m);
    red[tid] = v.x + v.y + v.z + v.w;
    __syncthreads();
    for (int s = 128; s > 0; s >>= 1) {
        if (tid < s) red[tid] += red[tid + s];
        __syncthreads();
    }
    const float inv = 1.0f / red[0];
    v.x *= inv; v.y *= inv; v.z *= inv; v.w *= inv;

    __nv_bfloat162 h0 = __floats2bfloat162_rn(v.x, v.y);
    __nv_bfloat162 h1 = __floats2bfloat162_rn(v.z, v.w);
    float lx = v.x - __bfloat162float(h0.x);
    float ly = v.y - __bfloat162float(h0.y);
    float lz = v.z - __bfloat162float(h1.x);
    float lw = v.w - __bfloat162float(h1.y);
    ((__nv_bfloat162*)(Phi + row * NDIM))[tid * 2]     = h0;
    ((__nv_bfloat162*)(Phi + row * NDIM))[tid * 2 + 1] = h1;
    ((__nv_bfloat162*)(Plo + row * NDIM))[tid * 2]     = __floats2bfloat162_rn(lx, ly);
    ((__nv_bfloat162*)(Plo + row * NDIM))[tid * 2 + 1] = __floats2bfloat162_rn(lz, lw);
}

// ============================================================================
// 4) Split-bf16 NT GEMM via mma.sync. CTA tile 128x128, K-chunk 32, 2-stage
//    cp.async, 8 warps = 2(M) x 4(N), warp tile 64x32, 2 CTAs/SM.
// ============================================================================
#define KC 32
#define NCHUNK (NDIM / KC)     // 32
#define TILE_B 8192            // 128 rows x 64B (32 bf16)
#define STAGE_B 32768          // Ahi, Alo, Bhi, Blo
#define SMEM_DYN (1024 + 2 * STAGE_B)

template<bool RES>
__global__ __launch_bounds__(256, 2)
void cam_mma_kernel(const __nv_bfloat16* __restrict__ Ahi_g, const __nv_bfloat16* __restrict__ Alo_g,
                    const __nv_bfloat16* __restrict__ Bhi_g, const __nv_bfloat16* __restrict__ Blo_g,
                    const float* __restrict__ resid, float* __restrict__ outp)
{
    extern __shared__ char smem_raw[];
    char* sbase_p = (char*)((((uintptr_t)smem_raw) + 1023) & ~(uintptr_t)1023);
    const uint32_t sbase = smem_u32(sbase_p);

    const int tid = threadIdx.x;
    const int l   = tid & 31;
    const int wid = tid >> 5;
    const int m0  = (wid >> 2) * 64;
    const int n0  = (wid & 3) * 32;

    const size_t bofs = (size_t)blockIdx.z * NDIM * NDIM;
    const int row0 = blockIdx.y * 128;
    const int col0 = blockIdx.x * 128;
    const __nv_bfloat16* s0 = Ahi_g + bofs + (size_t)row0 * NDIM;
    const __nv_bfloat16* s1 = Alo_g + bofs + (size_t)row0 * NDIM;
    const __nv_bfloat16* s2 = Bhi_g + bofs + (size_t)col0 * NDIM;
    const __nv_bfloat16* s3 = Blo_g + bofs + (size_t)col0 * NDIM;

    // loader: per tile 512 x 16B chunks; 256 threads x 2 each
    auto load_chunk = [&](int c, int buf) {
        const int k0 = c * KC;
        const uint32_t stage = sbase + (uint32_t)buf * STAGE_B;
#pragma unroll
        for (int t = 0; t < 4; t++) {
            const __nv_bfloat16* sp = (t == 0) ? s0 : (t == 1) ? s1 : (t == 2) ? s2 : s3;
#pragma unroll
            for (int jj = 0; jj < 2; jj++) {
                int slot = tid + 256 * jj;        // 0..511
                int row  = slot >> 2;             // 0..127
                int ch   = slot & 3;              // 16B chunk in 64B row
                uint32_t dst = swz64(stage + (uint32_t)t * TILE_B, row, ch);
                const __nv_bfloat16* src = sp + (size_t)row * NDIM + k0 + ch * 8;
                asm volatile("cp.async.cg.shared.global [%0], [%1], 16;"
                             :: "r"(dst), "l"(src));
            }
        }
        asm volatile("cp.async.commit_group;" ::: "memory");
    };

    float acc[4][4][4];
#pragma unroll
    for (int i = 0; i < 4; i++)
#pragma unroll
        for (int j = 0; j < 4; j++)
#pragma unroll
            for (int q = 0; q < 4; q++) acc[i][j][q] = 0.f;

    const int a_row = l & 15;
    const int a_cs  = l >> 4;                       // 0/1
    const int b_row = (l & 7) + ((l >> 4) << 3);    // 0..15
    const int b_cs  = (l >> 3) & 1;                 // 0/1

    load_chunk(0, 0);
    load_chunk(1, 1);

    for (int c = 0; c < NCHUNK; c++) {
        const int buf = c & 1;
        if (c >= NCHUNK - 2) { asm volatile("cp.async.wait_group 0;" ::: "memory"); }
        else                 { asm volatile("cp.async.wait_group 1;" ::: "memory"); }
        __syncthreads();

        const uint32_t st  = sbase + (uint32_t)buf * STAGE_B;
        const uint32_t aHi = st;
        const uint32_t aLo = st + TILE_B;
        const uint32_t bHi = st + 2 * TILE_B;
        const uint32_t bLo = st + 3 * TILE_B;

#pragma unroll
        for (int k16 = 0; k16 < 2; k16++) {
            const int chA = 2 * k16 + a_cs;
            const int chB = 2 * k16 + b_cs;

            // hi/hi and hi/lo terms first (ah, bh, bl live)
            uint32_t ah[4][4];
#pragma unroll
            for (int i = 0; i < 4; i++) {
                const int r = m0 + i * 16 + a_row;
                LDSM4(ah[i][0], ah[i][1], ah[i][2], ah[i][3], swz64(aHi, r, chA));
            }
            uint32_t bh[4][2], bl[4][2];
#pragma unroll
            for (int j = 0; j < 2; j++) {
                const int r = n0 + j * 16 + b_row;
                LDSM4(bh[2*j][0], bh[2*j][1], bh[2*j+1][0], bh[2*j+1][1], swz64(bHi, r, chB));
                LDSM4(bl[2*j][0], bl[2*j][1], bl[2*j+1][0], bl[2*j+1][1], swz64(bLo, r, chB));
            }
#pragma unroll
            for (int i = 0; i < 4; i++)
#pragma unroll
                for (int j = 0; j < 4; j++) {
                    MMA16816(acc[i][j], ah[i], bh[j][0], bh[j][1]);
                    MMA16816(acc[i][j], ah[i], bl[j][0], bl[j][1]);
                }
            // lo/hi term (al replaces ah; bl dead)
            uint32_t al[4][4];
#pragma unroll
            for (int i = 0; i < 4; i++) {
                const int r = m0 + i * 16 + a_row;
                LDSM4(al[i][0], al[i][1], al[i][2], al[i][3], swz64(aLo, r, chA));
            }
#pragma unroll
            for (int i = 0; i < 4; i++)
#pragma unroll
                for (int j = 0; j < 4; j++)
                    MMA16816(acc[i][j], al[i], bh[j][0], bh[j][1]);
        }
        __syncthreads();
        if (c + 2 < NCHUNK) load_chunk(c + 2, buf);
    }

    // ---- epilogue: regs -> gmem (float2, fused residual) ----
    float* outb = outp + bofs;
    const float* resb = resid + bofs;
    const int er = l >> 2;
    const int ec = (l & 3) * 2;

#pragma unroll
    for (int i = 0; i < 4; i++) {
        const int grow = row0 + m0 + i * 16 + er;
#pragma unroll
        for (int j = 0; j < 4; j++) {
            const int gcol = col0 + n0 + j * 8 + ec;
            size_t o0 = (size_t)grow * NDIM + gcol;
            size_t o1 = (size_t)(grow + 8) * NDIM + gcol;
            float2 v0 = make_float2(acc[i][j][0], acc[i][j][1]);
            float2 v1 = make_float2(acc[i][j][2], acc[i][j][3]);
            if (RES) {
                float2 r0 = *(const float2*)(resb + o0);
                float2 r1 = *(const float2*)(resb + o1);
                v0.x += r0.x; v0.y += r0.y;
                v1.x += r1.x; v1.y += r1.y;
            }
            *(float2*)(outb + o0) = v0;
            *(float2*)(outb + o1) = v1;
        }
    }
}

// ============================================================================
extern "C" void kernel_launch(void* const* d_in, const int* in_sizes, int n_in,
                              void* d_out, int out_size) {
    const float* a = (const float*)d_in[0];
    const float* b = (const float*)d_in[1];
    const float* c = (const float*)d_in[2];
    float* out = (float*)d_out;

    __nv_bfloat16 *b_hi, *b_lo, *c_hi, *c_lo, *at_hi, *at_lo, *p_hi, *p_lo;
    float* scores;
    cudaGetSymbolAddress((void**)&b_hi, g_b_hi);
    cudaGetSymbolAddress((void**)&b_lo, g_b_lo);
    cudaGetSymbolAddress((void**)&c_hi, g_c_hi);
    cudaGetSymbolAddress((void**)&c_lo, g_c_lo);
    cudaGetSymbolAddress((void**)&at_hi, g_at_hi);
    cudaGetSymbolAddress((void**)&at_lo, g_at_lo);
    cudaGetSymbolAddress((void**)&p_hi, g_p_hi);
    cudaGetSymbolAddress((void**)&p_lo, g_p_lo);
    cudaGetSymbolAddress((void**)&scores, g_scores);

    cudaFuncSetAttribute((const void*)cam_mma_kernel<false>,
                         cudaFuncAttributeMaxDynamicSharedMemorySize, SMEM_DYN);
    cudaFuncSetAttribute((const void*)cam_mma_kernel<true>,
                         cudaFuncAttributeMaxDynamicSharedMemorySize, SMEM_DYN);

    const int n4 = (BATCH * NDIM * NDIM) / 4;
    split_bf16_2<<<dim3(n4 / 256, 2), 256>>>(b, c, b_hi, b_lo, c_hi, c_lo);
    transpose_split<<<dim3(32, 32, BATCH), dim3(32, 8)>>>(a, at_hi, at_lo);

    dim3 grid(8, 8, BATCH);
    cam_mma_kernel<false><<<grid, 256, SMEM_DYN>>>(b_hi, b_lo, c_hi, c_lo, a, scores);
    cam_softmax<<<BATCH * NDIM, 256>>>(scores, p_hi, p_lo);
    cam_mma_kernel<true><<<grid, 256, SMEM_DYN>>>(p_hi, p_lo, at_hi, at_lo, a, out);
}

// round 5
// speedup vs baseline: 3.0869x; 1.0193x over previous
#include <cuda_runtime.h>
#include <cuda_bf16.h>
#include <cstdint>

// ============================================================================
// CAM: scores = b@c^T (NT), P = softmax(scores), out = P@a + a   per batch.
// B=16, C=1024, HW=1024. Split-bf16 mma.sync GEMMs (hi*hi + hi*lo + lo*hi),
// fp32 accumulate. Base-ISA only (harness targets sm_103, no tcgen05).
// R5: 3-stage cp.async pipeline, 1 sync/chunk, free regs; shuffle softmax.
// ============================================================================

#define BATCH 16
#define NDIM 1024

// -------- scratch (device globals; no allocation allowed) --------
__device__ __nv_bfloat16 g_b_hi[(size_t)BATCH * NDIM * NDIM];
__device__ __nv_bfloat16 g_b_lo[(size_t)BATCH * NDIM * NDIM];
__device__ __nv_bfloat16 g_c_hi[(size_t)BATCH * NDIM * NDIM];
__device__ __nv_bfloat16 g_c_lo[(size_t)BATCH * NDIM * NDIM];
__device__ __nv_bfloat16 g_at_hi[(size_t)BATCH * NDIM * NDIM];
__device__ __nv_bfloat16 g_at_lo[(size_t)BATCH * NDIM * NDIM];
__device__ __nv_bfloat16 g_p_hi[(size_t)BATCH * NDIM * NDIM];
__device__ __nv_bfloat16 g_p_lo[(size_t)BATCH * NDIM * NDIM];
__device__ float g_scores[(size_t)BATCH * NDIM * NDIM];

__device__ __forceinline__ uint32_t smem_u32(const void* p) {
    uint32_t a;
    asm("{ .reg .u64 t; cvta.to.shared.u64 t, %1; cvt.u32.u64 %0, t; }"
        : "=r"(a) : "l"(p));
    return a;
}

#define LDSM4(r0, r1, r2, r3, addr) \
    asm volatile("ldmatrix.sync.aligned.m8n8.x4.shared.b16 {%0,%1,%2,%3}, [%4];" \
                 : "=r"(r0), "=r"(r1), "=r"(r2), "=r"(r3) : "r"(addr))

#define MMA16816(d, a, bb0, bb1) \
    asm volatile("mma.sync.aligned.m16n8k16.row.col.f32.bf16.bf16.f32 " \
                 "{%0,%1,%2,%3}, {%4,%5,%6,%7}, {%8,%9}, {%0,%1,%2,%3};" \
                 : "+f"((d)[0]), "+f"((d)[1]), "+f"((d)[2]), "+f"((d)[3]) \
                 : "r"((a)[0]), "r"((a)[1]), "r"((a)[2]), "r"((a)[3]), \
                   "r"(bb0), "r"(bb1))

// SW128 swizzle, 128B rows: chunk' = chunk ^ (row & 7)
__device__ __forceinline__ uint32_t swz(uint32_t base, int row, int ch) {
    return base + (uint32_t)(row * 128) + (uint32_t)(((ch ^ (row & 7)) & 7) * 16);
}

// ============================================================================
// 1) Fused split fp32 -> bf16 hi/lo for b and c (grid.y selects tensor)
// ============================================================================
__global__ __launch_bounds__(256)
void split_bf16_2(const float* __restrict__ b, const float* __restrict__ c,
                  __nv_bfloat16* __restrict__ b_hi, __nv_bfloat16* __restrict__ b_lo,
                  __nv_bfloat16* __restrict__ c_hi, __nv_bfloat16* __restrict__ c_lo) {
    const float* src = blockIdx.y ? c : b;
    __nv_bfloat16* hi = blockIdx.y ? c_hi : b_hi;
    __nv_bfloat16* lo = blockIdx.y ? c_lo : b_lo;
    size_t i = (size_t)blockIdx.x * blockDim.x + threadIdx.x;
    float4 v = ((const float4*)src)[i];
    __nv_bfloat162 h0 = __floats2bfloat162_rn(v.x, v.y);
    __nv_bfloat162 h1 = __floats2bfloat162_rn(v.z, v.w);
    float lx = v.x - __bfloat162float(h0.x);
    float ly = v.y - __bfloat162float(h0.y);
    float lz = v.z - __bfloat162float(h1.x);
    float lw = v.w - __bfloat162float(h1.y);
    ((__nv_bfloat162*)hi)[i * 2]     = h0;
    ((__nv_bfloat162*)hi)[i * 2 + 1] = h1;
    ((__nv_bfloat162*)lo)[i * 2]     = __floats2bfloat162_rn(lx, ly);
    ((__nv_bfloat162*)lo)[i * 2 + 1] = __floats2bfloat162_rn(lz, lw);
}

// ============================================================================
// 2) Transpose a[b][ch][hw] -> a_t[b][hw][ch], split to bf16 hi/lo
// ============================================================================
__global__ __launch_bounds__(256)
void transpose_split(const float* __restrict__ a, __nv_bfloat16* __restrict__ at_hi,
                     __nv_bfloat16* __restrict__ at_lo) {
    __shared__ float tile[32][33];
    const size_t base = (size_t)blockIdx.z * NDIM * NDIM;
    const int tx = threadIdx.x, ty = threadIdx.y;
    const int x = blockIdx.x * 32 + tx;
    const int y0 = blockIdx.y * 32;
#pragma unroll
    for (int j = 0; j < 4; j++)
        tile[ty + j * 8][tx] = a[base + (size_t)(y0 + ty + j * 8) * NDIM + x];
    __syncthreads();
    const int x2 = blockIdx.y * 32 + tx;
    const int y20 = blockIdx.x * 32;
#pragma unroll
    for (int j = 0; j < 4; j++) {
        float v = tile[tx][ty + j * 8];
        __nv_bfloat16 h = __float2bfloat16(v);
        float l = v - __bfloat162float(h);
        size_t o = base + (size_t)(y20 + ty + j * 8) * NDIM + x2;
        at_hi[o] = h;
        at_lo[o] = __float2bfloat16(l);
    }
}

// ============================================================================
// 3) Row softmax (1024) -> bf16 hi/lo P, shuffle reductions
// ============================================================================
__global__ __launch_bounds__(256)
void cam_softmax(const float* __restrict__ S, __nv_bfloat16* __restrict__ Phi,
                 __nv_bfloat16* __restrict__ Plo) {
    __shared__ float wred[8];
    const size_t row = blockIdx.x;
    const float* p = S + row * NDIM;
    const int tid = threadIdx.x;
    const int lane = tid & 31;
    const int warp = tid >> 5;

    float4 v = *(const float4*)(p + tid * 4);
    float m = fmaxf(fmaxf(v.x, v.y), fmaxf(v.z, v.w));
#pragma unroll
    for (int off = 16; off > 0; off >>= 1)
        m = fmaxf(m, __shfl_xor_sync(0xFFFFFFFFu, m, off));
    if (lane == 0) wred[warp] = m;
    __syncthreads();
    m = wred[0];
#pragma unroll
    for (int w = 1; w < 8; w++) m = fmaxf(m, wred[w]);
    __syncthreads();

    v.x = __expf(v.x - m); v.y = __expf(v.y - m);
    v.z = __expf(v.z - m); v.w = __expf(v.w - m);
    float s = v.x + v.y + v.z + v.w;
#pragma unroll
    for (int off = 16; off > 0; off >>= 1)
        s += __shfl_xor_sync(0xFFFFFFFFu, s, off);
    if (lane == 0) wred[warp] = s;
    __syncthreads();
    s = 0.f;
#pragma unroll
    for (int w = 0; w < 8; w++) s += wred[w];
    const float inv = 1.0f / s;
    v.x *= inv; v.y *= inv; v.z *= inv; v.w *= inv;

    __nv_bfloat162 h0 = __floats2bfloat162_rn(v.x, v.y);
    __nv_bfloat162 h1 = __floats2bfloat162_rn(v.z, v.w);
    float lx = v.x - __bfloat162float(h0.x);
    float ly = v.y - __bfloat162float(h0.y);
    float lz = v.z - __bfloat162float(h1.x);
    float lw = v.w - __bfloat162float(h1.y);
    ((__nv_bfloat162*)(Phi + row * NDIM))[tid * 2]     = h0;
    ((__nv_bfloat162*)(Phi + row * NDIM))[tid * 2 + 1] = h1;
    ((__nv_bfloat162*)(Plo + row * NDIM))[tid * 2]     = __floats2bfloat162_rn(lx, ly);
    ((__nv_bfloat162*)(Plo + row * NDIM))[tid * 2 + 1] = __floats2bfloat162_rn(lz, lw);
}

// ============================================================================
// 4) Split-bf16 NT GEMM via mma.sync. CTA tile 128x128, KC=64, 3-stage
//    cp.async pipeline, ONE sync per chunk, 8 warps = 2(M) x 4(N).
// ============================================================================
#define KC 64
#define NCHUNK (NDIM / KC)     // 16
#define TILE_B 16384           // 128 rows x 128B (64 bf16)
#define STAGE_B 65536          // Ahi, Alo, Bhi, Blo
#define NSTAGE 3
#define SMEM_DYN (1024 + NSTAGE * STAGE_B)

template<bool RES>
__global__ __launch_bounds__(256, 1)
void cam_mma_kernel(const __nv_bfloat16* __restrict__ Ahi_g, const __nv_bfloat16* __restrict__ Alo_g,
                    const __nv_bfloat16* __restrict__ Bhi_g, const __nv_bfloat16* __restrict__ Blo_g,
                    const float* __restrict__ resid, float* __restrict__ outp)
{
    extern __shared__ char smem_raw[];
    char* sbase_p = (char*)((((uintptr_t)smem_raw) + 1023) & ~(uintptr_t)1023);
    const uint32_t sbase = smem_u32(sbase_p);

    const int tid = threadIdx.x;
    const int l   = tid & 31;
    const int wid = tid >> 5;
    const int m0  = (wid >> 2) * 64;
    const int n0  = (wid & 3) * 32;

    const size_t bofs = (size_t)blockIdx.z * NDIM * NDIM;
    const int row0 = blockIdx.y * 128;
    const int col0 = blockIdx.x * 128;
    const __nv_bfloat16* s0 = Ahi_g + bofs + (size_t)row0 * NDIM;
    const __nv_bfloat16* s1 = Alo_g + bofs + (size_t)row0 * NDIM;
    const __nv_bfloat16* s2 = Bhi_g + bofs + (size_t)col0 * NDIM;
    const __nv_bfloat16* s3 = Blo_g + bofs + (size_t)col0 * NDIM;

    // loader: per tile 1024 x 16B chunks; 256 threads x 4 each
    auto load_chunk = [&](int c, int buf) {
        const int k0 = c * KC;
        const uint32_t stage = sbase + (uint32_t)buf * STAGE_B;
#pragma unroll
        for (int t = 0; t < 4; t++) {
            const __nv_bfloat16* sp = (t == 0) ? s0 : (t == 1) ? s1 : (t == 2) ? s2 : s3;
#pragma unroll
            for (int jj = 0; jj < 4; jj++) {
                int slot = tid + 256 * jj;        // 0..1023
                int row  = slot >> 3;             // 0..127
                int k16  = slot & 7;              // 16B chunk in 128B row
                uint32_t dst = swz(stage + (uint32_t)t * TILE_B, row, k16);
                const __nv_bfloat16* src = sp + (size_t)row * NDIM + k0 + k16 * 8;
                asm volatile("cp.async.cg.shared.global [%0], [%1], 16;"
                             :: "r"(dst), "l"(src));
            }
        }
        asm volatile("cp.async.commit_group;" ::: "memory");
    };

    float acc[4][4][4];
#pragma unroll
    for (int i = 0; i < 4; i++)
#pragma unroll
        for (int j = 0; j < 4; j++)
#pragma unroll
            for (int q = 0; q < 4; q++) acc[i][j][q] = 0.f;

    const int a_row = l & 15;
    const int a_cs  = l >> 4;                       // 0/1
    const int b_row = (l & 7) + ((l >> 4) << 3);    // 0..15
    const int b_cs  = (l >> 3) & 1;                 // 0/1

    load_chunk(0, 0);
    load_chunk(1, 1);

    int buf = 0;
    for (int c = 0; c < NCHUNK; c++) {
        // group for chunk c must be complete; pending groups are {c, c+1}
        // except on the last iteration where only {c} remains.
        if (c == NCHUNK - 1) { asm volatile("cp.async.wait_group 0;" ::: "memory"); }
        else                 { asm volatile("cp.async.wait_group 1;" ::: "memory"); }
        __syncthreads();   // all data for chunk c visible; stage (c+2)%3 free

        if (c + 2 < NCHUNK) {
            int nbuf = buf + 2; if (nbuf >= NSTAGE) nbuf -= NSTAGE;
            load_chunk(c + 2, nbuf);
        }

        const uint32_t st  = sbase + (uint32_t)buf * STAGE_B;
        const uint32_t aHi = st;
        const uint32_t aLo = st + TILE_B;
        const uint32_t bHi = st + 2 * TILE_B;
        const uint32_t bLo = st + 3 * TILE_B;

#pragma unroll
        for (int k16 = 0; k16 < 4; k16++) {
            const int chA = 2 * k16 + a_cs;
            const int chB = 2 * k16 + b_cs;

            uint32_t ah[4][4];
#pragma unroll
            for (int i = 0; i < 4; i++) {
                const int r = m0 + i * 16 + a_row;
                LDSM4(ah[i][0], ah[i][1], ah[i][2], ah[i][3], swz(aHi, r, chA));
            }
            uint32_t bh[4][2], bl[4][2];
#pragma unroll
            for (int j = 0; j < 2; j++) {
                const int r = n0 + j * 16 + b_row;
                LDSM4(bh[2*j][0], bh[2*j][1], bh[2*j+1][0], bh[2*j+1][1], swz(bHi, r, chB));
                LDSM4(bl[2*j][0], bl[2*j][1], bl[2*j+1][0], bl[2*j+1][1], swz(bLo, r, chB));
            }
#pragma unroll
            for (int i = 0; i < 4; i++)
#pragma unroll
                for (int j = 0; j < 4; j++) {
                    MMA16816(acc[i][j], ah[i], bh[j][0], bh[j][1]);
                    MMA16816(acc[i][j], ah[i], bl[j][0], bl[j][1]);
                }
            uint32_t al[4][4];
#pragma unroll
            for (int i = 0; i < 4; i++) {
                const int r = m0 + i * 16 + a_row;
                LDSM4(al[i][0], al[i][1], al[i][2], al[i][3], swz(aLo, r, chA));
            }
#pragma unroll
            for (int i = 0; i < 4; i++)
#pragma unroll
                for (int j = 0; j < 4; j++)
                    MMA16816(acc[i][j], al[i], bh[j][0], bh[j][1]);
        }
        buf++; if (buf >= NSTAGE) buf = 0;
    }

    // ---- epilogue: regs -> gmem (float2, fused residual) ----
    float* outb = outp + bofs;
    const float* resb = resid + bofs;
    const int er = l >> 2;
    const int ec = (l & 3) * 2;

#pragma unroll
    for (int i = 0; i < 4; i++) {
        const int grow = row0 + m0 + i * 16 + er;
#pragma unroll
        for (int j = 0; j < 4; j++) {
            const int gcol = col0 + n0 + j * 8 + ec;
            size_t o0 = (size_t)grow * NDIM + gcol;
            size_t o1 = (size_t)(grow + 8) * NDIM + gcol;
            float2 v0 = make_float2(acc[i][j][0], acc[i][j][1]);
            float2 v1 = make_float2(acc[i][j][2], acc[i][j][3]);
            if (RES) {
                float2 r0 = *(const float2*)(resb + o0);
                float2 r1 = *(const float2*)(resb + o1);
                v0.x += r0.x; v0.y += r0.y;
                v1.x += r1.x; v1.y += r1.y;
            }
            *(float2*)(outb + o0) = v0;
            *(float2*)(outb + o1) = v1;
        }
    }
}

// ============================================================================
extern "C" void kernel_launch(void* const* d_in, const int* in_sizes, int n_in,
                              void* d_out, int out_size) {
    const float* a = (const float*)d_in[0];
    const float* b = (const float*)d_in[1];
    const float* c = (const float*)d_in[2];
    float* out = (float*)d_out;

    __nv_bfloat16 *b_hi, *b_lo, *c_hi, *c_lo, *at_hi, *at_lo, *p_hi, *p_lo;
    float* scores;
    cudaGetSymbolAddress((void**)&b_hi, g_b_hi);
    cudaGetSymbolAddress((void**)&b_lo, g_b_lo);
    cudaGetSymbolAddress((void**)&c_hi, g_c_hi);
    cudaGetSymbolAddress((void**)&c_lo, g_c_lo);
    cudaGetSymbolAddress((void**)&at_hi, g_at_hi);
    cudaGetSymbolAddress((void**)&at_lo, g_at_lo);
    cudaGetSymbolAddress((void**)&p_hi, g_p_hi);
    cudaGetSymbolAddress((void**)&p_lo, g_p_lo);
    cudaGetSymbolAddress((void**)&scores, g_scores);

    cudaFuncSetAttribute((const void*)cam_mma_kernel<false>,
                         cudaFuncAttributeMaxDynamicSharedMemorySize, SMEM_DYN);
    cudaFuncSetAttribute((const void*)cam_mma_kernel<true>,
                         cudaFuncAttributeMaxDynamicSharedMemorySize, SMEM_DYN);

    const int n4 = (BATCH * NDIM * NDIM) / 4;
    split_bf16_2<<<dim3(n4 / 256, 2), 256>>>(b, c, b_hi, b_lo, c_hi, c_lo);
    transpose_split<<<dim3(32, 32, BATCH), dim3(32, 8)>>>(a, at_hi, at_lo);

    dim3 grid(8, 8, BATCH);
    cam_mma_kernel<false><<<grid, 256, SMEM_DYN>>>(b_hi, b_lo, c_hi, c_lo, a, scores);
    cam_softmax<<<BATCH * NDIM, 256>>>(scores, p_hi, p_lo);
    cam_mma_kernel<true><<<grid, 256, SMEM_DYN>>>(p_hi, p_lo, at_hi, at_lo, a, out);
}

// round 6
// speedup vs baseline: 3.1567x; 1.0226x over previous
#include <cuda_runtime.h>
#include <cuda_bf16.h>
#include <cstdint>

// ============================================================================
// CAM: scores = b@c^T (NT), P = softmax(scores), out = P@a + a   per batch.
// B=16, C=1024, HW=1024. Split-bf16 mma.sync GEMMs (hi*hi + hi*lo + lo*hi),
// fp32 accumulate. Base-ISA only (harness targets sm_103, no tcgen05).
// R6: 2 CTAs/SM (reg-budgeted frag reuse), KC=32, 3-stage cp.async.
// ============================================================================

#define BATCH 16
#define NDIM 1024

// -------- scratch (device globals; no allocation allowed) --------
__device__ __nv_bfloat16 g_b_hi[(size_t)BATCH * NDIM * NDIM];
__device__ __nv_bfloat16 g_b_lo[(size_t)BATCH * NDIM * NDIM];
__device__ __nv_bfloat16 g_c_hi[(size_t)BATCH * NDIM * NDIM];
__device__ __nv_bfloat16 g_c_lo[(size_t)BATCH * NDIM * NDIM];
__device__ __nv_bfloat16 g_at_hi[(size_t)BATCH * NDIM * NDIM];
__device__ __nv_bfloat16 g_at_lo[(size_t)BATCH * NDIM * NDIM];
__device__ __nv_bfloat16 g_p_hi[(size_t)BATCH * NDIM * NDIM];
__device__ __nv_bfloat16 g_p_lo[(size_t)BATCH * NDIM * NDIM];
__device__ float g_scores[(size_t)BATCH * NDIM * NDIM];

__device__ __forceinline__ uint32_t smem_u32(const void* p) {
    uint32_t a;
    asm("{ .reg .u64 t; cvta.to.shared.u64 t, %1; cvt.u32.u64 %0, t; }"
        : "=r"(a) : "l"(p));
    return a;
}

#define LDSM4(r0, r1, r2, r3, addr) \
    asm volatile("ldmatrix.sync.aligned.m8n8.x4.shared.b16 {%0,%1,%2,%3}, [%4];" \
                 : "=r"(r0), "=r"(r1), "=r"(r2), "=r"(r3) : "r"(addr))

#define MMA16816(d, a, bb0, bb1) \
    asm volatile("mma.sync.aligned.m16n8k16.row.col.f32.bf16.bf16.f32 " \
                 "{%0,%1,%2,%3}, {%4,%5,%6,%7}, {%8,%9}, {%0,%1,%2,%3};" \
                 : "+f"((d)[0]), "+f"((d)[1]), "+f"((d)[2]), "+f"((d)[3]) \
                 : "r"((a)[0]), "r"((a)[1]), "r"((a)[2]), "r"((a)[3]), \
                   "r"(bb0), "r"(bb1))

// 64B-row swizzle: 4 chunks of 16B per row; conflict-free for ldmatrix
// (verified correct in R4): ch' = ch ^ ((row>>1)&3)
__device__ __forceinline__ uint32_t swz64(uint32_t base, int row, int ch) {
    return base + (uint32_t)(row * 64) +
           (uint32_t)(((ch ^ ((row >> 1) & 3)) & 3) * 16);
}

// ============================================================================
// 1) Fused split fp32 -> bf16 hi/lo for b and c (grid.y selects tensor)
// ============================================================================
__global__ __launch_bounds__(256)
void split_bf16_2(const float* __restrict__ b, const float* __restrict__ c,
                  __nv_bfloat16* __restrict__ b_hi, __nv_bfloat16* __restrict__ b_lo,
                  __nv_bfloat16* __restrict__ c_hi, __nv_bfloat16* __restrict__ c_lo) {
    const float* src = blockIdx.y ? c : b;
    __nv_bfloat16* hi = blockIdx.y ? c_hi : b_hi;
    __nv_bfloat16* lo = blockIdx.y ? c_lo : b_lo;
    size_t i = (size_t)blockIdx.x * blockDim.x + threadIdx.x;
    float4 v = ((const float4*)src)[i];
    __nv_bfloat162 h0 = __floats2bfloat162_rn(v.x, v.y);
    __nv_bfloat162 h1 = __floats2bfloat162_rn(v.z, v.w);
    float lx = v.x - __bfloat162float(h0.x);
    float ly = v.y - __bfloat162float(h0.y);
    float lz = v.z - __bfloat162float(h1.x);
    float lw = v.w - __bfloat162float(h1.y);
    ((__nv_bfloat162*)hi)[i * 2]     = h0;
    ((__nv_bfloat162*)hi)[i * 2 + 1] = h1;
    ((__nv_bfloat162*)lo)[i * 2]     = __floats2bfloat162_rn(lx, ly);
    ((__nv_bfloat162*)lo)[i * 2 + 1] = __floats2bfloat162_rn(lz, lw);
}

// ============================================================================
// 2) Transpose a[b][ch][hw] -> a_t[b][hw][ch], split to bf16 hi/lo
// ============================================================================
__global__ __launch_bounds__(256)
void transpose_split(const float* __restrict__ a, __nv_bfloat16* __restrict__ at_hi,
                     __nv_bfloat16* __restrict__ at_lo) {
    __shared__ float tile[32][33];
    const size_t base = (size_t)blockIdx.z * NDIM * NDIM;
    const int tx = threadIdx.x, ty = threadIdx.y;
    const int x = blockIdx.x * 32 + tx;
    const int y0 = blockIdx.y * 32;
#pragma unroll
    for (int j = 0; j < 4; j++)
        tile[ty + j * 8][tx] = a[base + (size_t)(y0 + ty + j * 8) * NDIM + x];
    __syncthreads();
    const int x2 = blockIdx.y * 32 + tx;
    const int y20 = blockIdx.x * 32;
#pragma unroll
    for (int j = 0; j < 4; j++) {
        float v = tile[tx][ty + j * 8];
        __nv_bfloat16 h = __float2bfloat16(v);
        float l = v - __bfloat162float(h);
        size_t o = base + (size_t)(y20 + ty + j * 8) * NDIM + x2;
        at_hi[o] = h;
        at_lo[o] = __float2bfloat16(l);
    }
}

// ============================================================================
// 3) Row softmax (1024) -> bf16 hi/lo P, shuffle reductions
// ============================================================================
__global__ __launch_bounds__(256)
void cam_softmax(const float* __restrict__ S, __nv_bfloat16* __restrict__ Phi,
                 __nv_bfloat16* __restrict__ Plo) {
    __shared__ float wred[8];
    const size_t row = blockIdx.x;
    const float* p = S + row * NDIM;
    const int tid = threadIdx.x;
    const int lane = tid & 31;
    const int warp = tid >> 5;

    float4 v = *(const float4*)(p + tid * 4);
    float m = fmaxf(fmaxf(v.x, v.y), fmaxf(v.z, v.w));
#pragma unroll
    for (int off = 16; off > 0; off >>= 1)
        m = fmaxf(m, __shfl_xor_sync(0xFFFFFFFFu, m, off));
    if (lane == 0) wred[warp] = m;
    __syncthreads();
    m = wred[0];
#pragma unroll
    for (int w = 1; w < 8; w++) m = fmaxf(m, wred[w]);
    __syncthreads();

    v.x = __expf(v.x - m); v.y = __expf(v.y - m);
    v.z = __expf(v.z - m); v.w = __expf(v.w - m);
    float s = v.x + v.y + v.z + v.w;
#pragma unroll
    for (int off = 16; off > 0; off >>= 1)
        s += __shfl_xor_sync(0xFFFFFFFFu, s, off);
    if (lane == 0) wred[warp] = s;
    __syncthreads();
    s = 0.f;
#pragma unroll
    for (int w = 0; w < 8; w++) s += wred[w];
    const float inv = 1.0f / s;
    v.x *= inv; v.y *= inv; v.z *= inv; v.w *= inv;

    __nv_bfloat162 h0 = __floats2bfloat162_rn(v.x, v.y);
    __nv_bfloat162 h1 = __floats2bfloat162_rn(v.z, v.w);
    float lx = v.x - __bfloat162float(h0.x);
    float ly = v.y - __bfloat162float(h0.y);
    float lz = v.z - __bfloat162float(h1.x);
    float lw = v.w - __bfloat162float(h1.y);
    ((__nv_bfloat162*)(Phi + row * NDIM))[tid * 2]     = h0;
    ((__nv_bfloat162*)(Phi + row * NDIM))[tid * 2 + 1] = h1;
    ((__nv_bfloat162*)(Plo + row * NDIM))[tid * 2]     = __floats2bfloat162_rn(lx, ly);
    ((__nv_bfloat162*)(Plo + row * NDIM))[tid * 2 + 1] = __floats2bfloat162_rn(lz, lw);
}

// ============================================================================
// 4) Split-bf16 NT GEMM via mma.sync. CTA tile 128x128, KC=32, 3-stage
//    cp.async, 8 warps = 2(M) x 4(N), warp tile 64x32, 2 CTAs/SM.
//    Register-budgeted: A-fragment array reused for hi then lo pass.
// ============================================================================
#define KC 32
#define NCHUNK (NDIM / KC)     // 32
#define TILE_B 8192            // 128 rows x 64B (32 bf16)
#define STAGE_B 32768          // Ahi, Alo, Bhi, Blo
#define NSTAGE 3
#define SMEM_DYN (1024 + NSTAGE * STAGE_B)

template<bool RES>
__global__ __launch_bounds__(256, 2)
void cam_mma_kernel(const __nv_bfloat16* __restrict__ Ahi_g, const __nv_bfloat16* __restrict__ Alo_g,
                    const __nv_bfloat16* __restrict__ Bhi_g, const __nv_bfloat16* __restrict__ Blo_g,
                    const float* __restrict__ resid, float* __restrict__ outp)
{
    extern __shared__ char smem_raw[];
    char* sbase_p = (char*)((((uintptr_t)smem_raw) + 1023) & ~(uintptr_t)1023);
    const uint32_t sbase = smem_u32(sbase_p);

    const int tid = threadIdx.x;
    const int l   = tid & 31;
    const int wid = tid >> 5;
    const int m0  = (wid >> 2) * 64;
    const int n0  = (wid & 3) * 32;

    const size_t bofs = (size_t)blockIdx.z * NDIM * NDIM;
    const int row0 = blockIdx.y * 128;
    const int col0 = blockIdx.x * 128;
    const __nv_bfloat16* s0 = Ahi_g + bofs + (size_t)row0 * NDIM;
    const __nv_bfloat16* s1 = Alo_g + bofs + (size_t)row0 * NDIM;
    const __nv_bfloat16* s2 = Bhi_g + bofs + (size_t)col0 * NDIM;
    const __nv_bfloat16* s3 = Blo_g + bofs + (size_t)col0 * NDIM;

    // loader: per tile 512 x 16B chunks; 4 tiles; 256 threads x 8 cp.async
    auto load_chunk = [&](int c, int buf) {
        const int k0 = c * KC;
        const uint32_t stage = sbase + (uint32_t)buf * STAGE_B;
#pragma unroll
        for (int t = 0; t < 4; t++) {
            const __nv_bfloat16* sp = (t == 0) ? s0 : (t == 1) ? s1 : (t == 2) ? s2 : s3;
#pragma unroll
            for (int jj = 0; jj < 2; jj++) {
                int slot = tid + 256 * jj;        // 0..511
                int row  = slot >> 2;             // 0..127
                int ch   = slot & 3;              // 16B chunk in 64B row
                uint32_t dst = swz64(stage + (uint32_t)t * TILE_B, row, ch);
                const __nv_bfloat16* src = sp + (size_t)row * NDIM + k0 + ch * 8;
                asm volatile("cp.async.cg.shared.global [%0], [%1], 16;"
                             :: "r"(dst), "l"(src));
            }
        }
        asm volatile("cp.async.commit_group;" ::: "memory");
    };

    float acc[4][4][4];
#pragma unroll
    for (int i = 0; i < 4; i++)
#pragma unroll
        for (int j = 0; j < 4; j++)
#pragma unroll
            for (int q = 0; q < 4; q++) acc[i][j][q] = 0.f;

    const int a_row = l & 15;
    const int a_cs  = l >> 4;                       // 0/1
    const int b_row = (l & 7) + ((l >> 4) << 3);    // 0..15
    const int b_cs  = (l >> 3) & 1;                 // 0/1

    load_chunk(0, 0);
    load_chunk(1, 1);

    int buf = 0;
    for (int c = 0; c < NCHUNK; c++) {
        if (c == NCHUNK - 1) { asm volatile("cp.async.wait_group 0;" ::: "memory"); }
        else                 { asm volatile("cp.async.wait_group 1;" ::: "memory"); }
        __syncthreads();

        if (c + 2 < NCHUNK) {
            int nbuf = buf + 2; if (nbuf >= NSTAGE) nbuf -= NSTAGE;
            load_chunk(c + 2, nbuf);
        }

        const uint32_t st  = sbase + (uint32_t)buf * STAGE_B;
        const uint32_t aHi = st;
        const uint32_t aLo = st + TILE_B;
        const uint32_t bHi = st + 2 * TILE_B;
        const uint32_t bLo = st + 3 * TILE_B;

#pragma unroll
        for (int k16 = 0; k16 < 2; k16++) {
            const int chA = 2 * k16 + a_cs;
            const int chB = 2 * k16 + b_cs;

            uint32_t af[4][4];                 // shared for hi then lo pass
            uint32_t bf[4][2], blf[4][2];
#pragma unroll
            for (int i = 0; i < 4; i++) {
                const int r = m0 + i * 16 + a_row;
                LDSM4(af[i][0], af[i][1], af[i][2], af[i][3], swz64(aHi, r, chA));
            }
#pragma unroll
            for (int j = 0; j < 2; j++) {
                const int r = n0 + j * 16 + b_row;
                LDSM4(bf[2*j][0], bf[2*j][1], bf[2*j+1][0], bf[2*j+1][1], swz64(bHi, r, chB));
                LDSM4(blf[2*j][0], blf[2*j][1], blf[2*j+1][0], blf[2*j+1][1], swz64(bLo, r, chB));
            }
#pragma unroll
            for (int i = 0; i < 4; i++)
#pragma unroll
                for (int j = 0; j < 4; j++) {
                    MMA16816(acc[i][j], af[i], bf[j][0], bf[j][1]);
                    MMA16816(acc[i][j], af[i], blf[j][0], blf[j][1]);
                }
            // reload A fragments with lo parts (reuse registers)
#pragma unroll
            for (int i = 0; i < 4; i++) {
                const int r = m0 + i * 16 + a_row;
                LDSM4(af[i][0], af[i][1], af[i][2], af[i][3], swz64(aLo, r, chA));
            }
#pragma unroll
            for (int i = 0; i < 4; i++)
#pragma unroll
                for (int j = 0; j < 4; j++)
                    MMA16816(acc[i][j], af[i], bf[j][0], bf[j][1]);
        }
        buf++; if (buf >= NSTAGE) buf = 0;
    }

    // ---- epilogue: regs -> gmem (float2, fused residual) ----
    float* outb = outp + bofs;
    const float* resb = resid + bofs;
    const int er = l >> 2;
    const int ec = (l & 3) * 2;

#pragma unroll
    for (int i = 0; i < 4; i++) {
        const int grow = row0 + m0 + i * 16 + er;
#pragma unroll
        for (int j = 0; j < 4; j++) {
            const int gcol = col0 + n0 + j * 8 + ec;
            size_t o0 = (size_t)grow * NDIM + gcol;
            size_t o1 = (size_t)(grow + 8) * NDIM + gcol;
            float2 v0 = make_float2(acc[i][j][0], acc[i][j][1]);
            float2 v1 = make_float2(acc[i][j][2], acc[i][j][3]);
            if (RES) {
                float2 r0 = *(const float2*)(resb + o0);
                float2 r1 = *(const float2*)(resb + o1);
                v0.x += r0.x; v0.y += r0.y;
                v1.x += r1.x; v1.y += r1.y;
            }
            *(float2*)(outb + o0) = v0;
            *(float2*)(outb + o1) = v1;
        }
    }
}

// ============================================================================
extern "C" void kernel_launch(void* const* d_in, const int* in_sizes, int n_in,
                              void* d_out, int out_size) {
    const float* a = (const float*)d_in[0];
    const float* b = (const float*)d_in[1];
    const float* c = (const float*)d_in[2];
    float* out = (float*)d_out;

    __nv_bfloat16 *b_hi, *b_lo, *c_hi, *c_lo, *at_hi, *at_lo, *p_hi, *p_lo;
    float* scores;
    cudaGetSymbolAddress((void**)&b_hi, g_b_hi);
    cudaGetSymbolAddress((void**)&b_lo, g_b_lo);
    cudaGetSymbolAddress((void**)&c_hi, g_c_hi);
    cudaGetSymbolAddress((void**)&c_lo, g_c_lo);
    cudaGetSymbolAddress((void**)&at_hi, g_at_hi);
    cudaGetSymbolAddress((void**)&at_lo, g_at_lo);
    cudaGetSymbolAddress((void**)&p_hi, g_p_hi);
    cudaGetSymbolAddress((void**)&p_lo, g_p_lo);
    cudaGetSymbolAddress((void**)&scores, g_scores);

    cudaFuncSetAttribute((const void*)cam_mma_kernel<false>,
                         cudaFuncAttributeMaxDynamicSharedMemorySize, SMEM_DYN);
    cudaFuncSetAttribute((const void*)cam_mma_kernel<true>,
                         cudaFuncAttributeMaxDynamicSharedMemorySize, SMEM_DYN);

    const int n4 = (BATCH * NDIM * NDIM) / 4;
    split_bf16_2<<<dim3(n4 / 256, 2), 256>>>(b, c, b_hi, b_lo, c_hi, c_lo);
    transpose_split<<<dim3(32, 32, BATCH), dim3(32, 8)>>>(a, at_hi, at_lo);

    dim3 grid(8, 8, BATCH);
    cam_mma_kernel<false><<<grid, 256, SMEM_DYN>>>(b_hi, b_lo, c_hi, c_lo, a, scores);
    cam_softmax<<<BATCH * NDIM, 256>>>(scores, p_hi, p_lo);
    cam_mma_kernel<true><<<grid, 256, SMEM_DYN>>>(p_hi, p_lo, at_hi, at_lo, a, out);
}